// round 2
// baseline (speedup 1.0000x reference)
#include <cuda_runtime.h>
#include <math.h>

// Problem dims
#define BB 64
#define CC 256
#define HWN 1024
#define SS 512
#define DD 256
#define TAUV 0.07f
#define SIGMA (1.0f/1024.0f)

// GEMM tiling
#define BM 128
#define BN 64
#define BK 16
#define BNP 68   // padded Bs row stride (floats): conflict-light + float4-aligned
#define NTHR 256

// ---------------- scratch (static device globals; no allocation) ----------------
__device__ float g_patches[(size_t)BB*HWN*DD];   // 64 MB  [b][p][d]
__device__ float g_tokens [(size_t)BB*SS*DD];    // 32 MB  [b][s][d]
__device__ float g_sim    [(size_t)BB*HWN*SS];   // 128 MB [b][p][s]
__device__ float g_lgve   [(size_t)BB*SS*DD];    // 32 MB
__device__ float g_lnv    [(size_t)BB*SS*DD];    // 32 MB
__device__ float g_lnt    [(size_t)BB*SS*DD];    // 32 MB
__device__ float g_fsim   [(size_t)BB*SS*SS];    // 64 MB  [b][i][j]
__device__ float g_partV[BB*8*DD];
__device__ float g_partT[BB*4*DD];
__device__ float g_gimg[BB*DD];
__device__ float g_gtxt[BB*DD];
__device__ float g_norms[128];
__device__ float g_gsim[64*64];
__device__ float g_mn  [BB*SS];
__device__ float g_rinv[BB*SS];
__device__ float g_zinv[BB*SS];
__device__ float g_rowterm[BB*SS];
__device__ float g_colterm[BB*SS];
__device__ float g_gloss;

// ---------------- shared GEMM microkernel ----------------
__device__ __forceinline__ void mm_tile(const float (*As)[BM], const float* Bs,
                                        int tx, int ty, float acc[8][4]) {
#pragma unroll
    for (int kk = 0; kk < BK; kk++) {
        float4 a0 = *(const float4*)&As[kk][ty*8];
        float4 a1 = *(const float4*)&As[kk][ty*8 + 4];
        float4 b0 = *(const float4*)&Bs[kk*BNP + tx*4];
        float a[8] = {a0.x,a0.y,a0.z,a0.w,a1.x,a1.y,a1.z,a1.w};
        float bb[4] = {b0.x,b0.y,b0.z,b0.w};
#pragma unroll
        for (int i = 0; i < 8; i++)
#pragma unroll
            for (int j = 0; j < 4; j++)
                acc[i][j] = fmaf(a[i], bb[j], acc[i][j]);
    }
}

// ---------------- K1: patches = (img^T) @ Wv^T + bv ----------------
// A[p,c] = img[b][c][p] (contig in p); B[d,c] = Wv; C = g_patches[b][p][d]
__global__ void k_patch_adapter(const float* __restrict__ img,
                                const float* __restrict__ Wv,
                                const float* __restrict__ bv) {
    __shared__ float As[BK][BM];
    __shared__ float Bs[BK*BNP];
    int b = blockIdx.z;
    int p0 = blockIdx.x * BM, n0 = blockIdx.y * BN;
    int t = threadIdx.x, tx = t & 15, ty = t >> 4;
    float acc[8][4];
#pragma unroll
    for (int i = 0; i < 8; i++)
#pragma unroll
        for (int j = 0; j < 4; j++) acc[i][j] = 0.f;

    const float* Ab = img + (size_t)b * CC * HWN;
    for (int c0 = 0; c0 < CC; c0 += BK) {
#pragma unroll
        for (int i = 0; i < 8; i++) {
            int idx = t + i * 256;
            int m = idx & 127, k = idx >> 7;
            As[k][m] = Ab[(size_t)(c0 + k) * HWN + p0 + m];
        }
        {
            int n = t >> 2, kq = t & 3;
            float4 v = *(const float4*)&Wv[(size_t)(n0 + n) * DD + c0 + kq*4];
            Bs[(kq*4+0)*BNP + n] = v.x;
            Bs[(kq*4+1)*BNP + n] = v.y;
            Bs[(kq*4+2)*BNP + n] = v.z;
            Bs[(kq*4+3)*BNP + n] = v.w;
        }
        __syncthreads();
        mm_tile(As, Bs, tx, ty, acc);
        __syncthreads();
    }
    float* Cb = g_patches + (size_t)b * HWN * DD;
#pragma unroll
    for (int j = 0; j < 4; j++) {
        float bj = bv[n0 + tx*4 + j];
#pragma unroll
        for (int i = 0; i < 8; i++)
            Cb[(size_t)(p0 + ty*8 + i) * DD + n0 + tx*4 + j] = acc[i][j] + bj;
    }
}

// ---------------- K2: tokens = txt @ Wt^T + bt ----------------
__global__ void k_tok_adapter(const float* __restrict__ txt,
                              const float* __restrict__ Wt,
                              const float* __restrict__ bt) {
    __shared__ float As[BK][BM];
    __shared__ float Bs[BK*BNP];
    int b = blockIdx.z;
    int s0 = blockIdx.x * BM, n0 = blockIdx.y * BN;
    int t = threadIdx.x, tx = t & 15, ty = t >> 4;
    float acc[8][4];
#pragma unroll
    for (int i = 0; i < 8; i++)
#pragma unroll
        for (int j = 0; j < 4; j++) acc[i][j] = 0.f;

    for (int c0 = 0; c0 < DD; c0 += BK) {
        {
            int m = t >> 1, kh = t & 1;
            const float* row = txt + ((size_t)b * SS + s0 + m) * DD + c0 + kh*8;
            float4 v0 = *(const float4*)&row[0];
            float4 v1 = *(const float4*)&row[4];
            As[kh*8+0][m] = v0.x; As[kh*8+1][m] = v0.y;
            As[kh*8+2][m] = v0.z; As[kh*8+3][m] = v0.w;
            As[kh*8+4][m] = v1.x; As[kh*8+5][m] = v1.y;
            As[kh*8+6][m] = v1.z; As[kh*8+7][m] = v1.w;
        }
        {
            int n = t >> 2, kq = t & 3;
            float4 v = *(const float4*)&Wt[(size_t)(n0 + n) * DD + c0 + kq*4];
            Bs[(kq*4+0)*BNP + n] = v.x;
            Bs[(kq*4+1)*BNP + n] = v.y;
            Bs[(kq*4+2)*BNP + n] = v.z;
            Bs[(kq*4+3)*BNP + n] = v.w;
        }
        __syncthreads();
        mm_tile(As, Bs, tx, ty, acc);
        __syncthreads();
    }
    float* Cb = g_tokens + (size_t)b * SS * DD;
#pragma unroll
    for (int j = 0; j < 4; j++) {
        float bj = bt[n0 + tx*4 + j];
#pragma unroll
        for (int i = 0; i < 8; i++)
            Cb[(size_t)(s0 + ty*8 + i) * DD + n0 + tx*4 + j] = acc[i][j] + bj;
    }
}

// ---------------- K3: sim[b][p][s] = patches[b][p][:] . tokens[b][s][:] ----------------
__global__ void k_sim() {
    __shared__ float As[BK][BM];
    __shared__ float Bs[BK*BNP];
    int b = blockIdx.z;
    int p0 = blockIdx.x * BM, s0 = blockIdx.y * BN;
    int t = threadIdx.x, tx = t & 15, ty = t >> 4;
    float acc[8][4];
#pragma unroll
    for (int i = 0; i < 8; i++)
#pragma unroll
        for (int j = 0; j < 4; j++) acc[i][j] = 0.f;

    const float* pat = g_patches + (size_t)b * HWN * DD;
    const float* tok = g_tokens  + (size_t)b * SS  * DD;
    for (int c0 = 0; c0 < DD; c0 += BK) {
        {
            int m = t >> 1, kh = t & 1;
            const float* row = pat + (size_t)(p0 + m) * DD + c0 + kh*8;
            float4 v0 = *(const float4*)&row[0];
            float4 v1 = *(const float4*)&row[4];
            As[kh*8+0][m] = v0.x; As[kh*8+1][m] = v0.y;
            As[kh*8+2][m] = v0.z; As[kh*8+3][m] = v0.w;
            As[kh*8+4][m] = v1.x; As[kh*8+5][m] = v1.y;
            As[kh*8+6][m] = v1.z; As[kh*8+7][m] = v1.w;
        }
        {
            int n = t >> 2, kq = t & 3;
            float4 v = *(const float4*)&tok[(size_t)(s0 + n) * DD + c0 + kq*4];
            Bs[(kq*4+0)*BNP + n] = v.x;
            Bs[(kq*4+1)*BNP + n] = v.y;
            Bs[(kq*4+2)*BNP + n] = v.z;
            Bs[(kq*4+3)*BNP + n] = v.w;
        }
        __syncthreads();
        mm_tile(As, Bs, tx, ty, acc);
        __syncthreads();
    }
    float* Cb = g_sim + (size_t)b * HWN * SS;
#pragma unroll
    for (int i = 0; i < 8; i++)
#pragma unroll
        for (int j = 0; j < 4; j++)
            Cb[(size_t)(p0 + ty*8 + i) * SS + s0 + tx*4 + j] = acc[i][j];
}

// ---------------- column stats: min/max over p, then Z ----------------
__global__ void k_colstats() {
    int b = blockIdx.y;
    int tx = threadIdx.x, ty = threadIdx.y;
    int s = blockIdx.x * 32 + tx;
    const float* simb = g_sim + (size_t)b * HWN * SS;

    __shared__ float red0[8][32], red1[8][32];
    __shared__ float s_mn[32], s_rinv[32];

    float vmn = 1e30f, vmx = -1e30f;
    for (int p = ty; p < HWN; p += 8) {
        float v = simb[(size_t)p * SS + s];
        vmn = fminf(vmn, v);
        vmx = fmaxf(vmx, v);
    }
    red0[ty][tx] = vmn; red1[ty][tx] = vmx;
    __syncthreads();
    if (ty == 0) {
        float mn = red0[0][tx], mx = red1[0][tx];
#pragma unroll
        for (int q = 1; q < 8; q++) {
            mn = fminf(mn, red0[q][tx]);
            mx = fmaxf(mx, red1[q][tx]);
        }
        float rinv = 1.0f / (mx - mn + 1e-8f);
        s_mn[tx] = mn; s_rinv[tx] = rinv;
        g_mn[b*SS + s] = mn;
        g_rinv[b*SS + s] = rinv;
    }
    __syncthreads();
    float mn = s_mn[tx], rinv = s_rinv[tx];
    float z = 0.f;
    for (int p = ty; p < HWN; p += 8) {
        float v = simb[(size_t)p * SS + s];
        float tv = (v - mn) * rinv;
        if (tv >= SIGMA) z += tv;
    }
    red0[ty][tx] = z;
    __syncthreads();
    if (ty == 0) {
        float Z = red0[0][tx];
#pragma unroll
        for (int q = 1; q < 8; q++) Z += red0[q][tx];
        g_zinv[b*SS + s] = 1.0f / fmaxf(Z, 1e-12f);
    }
}

// ---------------- K4: lgve[b][s][d] = sum_p w(sim[b][p][s]) * patches[b][p][d] ----------------
__global__ void k_lgve() {
    __shared__ float As[BK][BM];
    __shared__ float Bs[BK*BNP];
    int b = blockIdx.z;
    int s0 = blockIdx.x * BM, n0 = blockIdx.y * BN;
    int t = threadIdx.x, tx = t & 15, ty = t >> 4;
    int mfix = t & 127;
    float mnv  = g_mn  [b*SS + s0 + mfix];
    float rinv = g_rinv[b*SS + s0 + mfix];
    float zinv = g_zinv[b*SS + s0 + mfix];
    float acc[8][4];
#pragma unroll
    for (int i = 0; i < 8; i++)
#pragma unroll
        for (int j = 0; j < 4; j++) acc[i][j] = 0.f;

    const float* simb = g_sim     + (size_t)b * HWN * SS;
    const float* pat  = g_patches + (size_t)b * HWN * DD;
    for (int p0 = 0; p0 < HWN; p0 += BK) {
#pragma unroll
        for (int i = 0; i < 8; i++) {
            int k = (t >> 7) + i * 2;
            float v = simb[(size_t)(p0 + k) * SS + s0 + mfix];
            float tv = (v - mnv) * rinv;
            tv = (tv < SIGMA) ? 0.f : tv;
            As[k][mfix] = tv * zinv;
        }
#pragma unroll
        for (int i = 0; i < 4; i++) {
            int idx = t + i * 256;
            int n = idx & 63, k = idx >> 6;
            Bs[k*BNP + n] = pat[(size_t)(p0 + k) * DD + n0 + n];
        }
        __syncthreads();
        mm_tile(As, Bs, tx, ty, acc);
        __syncthreads();
    }
    float* Cb = g_lgve + (size_t)b * SS * DD;
#pragma unroll
    for (int i = 0; i < 8; i++)
#pragma unroll
        for (int j = 0; j < 4; j++)
            Cb[(size_t)(s0 + ty*8 + i) * DD + n0 + tx*4 + j] = acc[i][j];
}

// ---------------- row L2 normalize (which=0: lgve->lnv, which=1: tokens->lnt) ----------------
__global__ void k_l2norm(int which) {
    const float* in  = which ? g_tokens : g_lgve;
    float*       out = which ? g_lnt    : g_lnv;
    int warp = threadIdx.x >> 5, lane = threadIdx.x & 31;
    size_t r = (size_t)blockIdx.x * 8 + warp;
    const float* row = in + r * DD;
    float v[8];
    float s = 0.f;
#pragma unroll
    for (int q = 0; q < 8; q++) { v[q] = row[lane + q*32]; s += v[q]*v[q]; }
#pragma unroll
    for (int off = 16; off > 0; off >>= 1) s += __shfl_xor_sync(0xffffffffu, s, off);
    float inv = 1.0f / fmaxf(sqrtf(s), 1e-8f);
#pragma unroll
    for (int q = 0; q < 8; q++) out[r * DD + lane + q*32] = v[q] * inv;
}

// ---------------- K5: fsim[b][i][j] = lnv[b][i][:].lnt[b][j][:] / TAU ----------------
__global__ void k_fsim() {
    __shared__ float As[BK][BM];
    __shared__ float Bs[BK*BNP];
    int b = blockIdx.z;
    int i0 = blockIdx.x * BM, j0 = blockIdx.y * BN;
    int t = threadIdx.x, tx = t & 15, ty = t >> 4;
    float acc[8][4];
#pragma unroll
    for (int i = 0; i < 8; i++)
#pragma unroll
        for (int j = 0; j < 4; j++) acc[i][j] = 0.f;

    const float* av = g_lnv + (size_t)b * SS * DD;
    const float* bv2 = g_lnt + (size_t)b * SS * DD;
    for (int c0 = 0; c0 < DD; c0 += BK) {
        {
            int m = t >> 1, kh = t & 1;
            const float* row = av + (size_t)(i0 + m) * DD + c0 + kh*8;
            float4 v0 = *(const float4*)&row[0];
            float4 v1 = *(const float4*)&row[4];
            As[kh*8+0][m] = v0.x; As[kh*8+1][m] = v0.y;
            As[kh*8+2][m] = v0.z; As[kh*8+3][m] = v0.w;
            As[kh*8+4][m] = v1.x; As[kh*8+5][m] = v1.y;
            As[kh*8+6][m] = v1.z; As[kh*8+7][m] = v1.w;
        }
        {
            int n = t >> 2, kq = t & 3;
            float4 v = *(const float4*)&bv2[(size_t)(j0 + n) * DD + c0 + kq*4];
            Bs[(kq*4+0)*BNP + n] = v.x;
            Bs[(kq*4+1)*BNP + n] = v.y;
            Bs[(kq*4+2)*BNP + n] = v.z;
            Bs[(kq*4+3)*BNP + n] = v.w;
        }
        __syncthreads();
        mm_tile(As, Bs, tx, ty, acc);
        __syncthreads();
    }
    const float itau = 1.0f / TAUV;
    float* Cb = g_fsim + (size_t)b * SS * SS;
#pragma unroll
    for (int i = 0; i < 8; i++)
#pragma unroll
        for (int j = 0; j < 4; j++)
            Cb[(size_t)(i0 + ty*8 + i) * SS + j0 + tx*4 + j] = acc[i][j] * itau;
}

// ---------------- mean-pool partials ----------------
__global__ void k_meanp() {
    int ch = blockIdx.x, b = blockIdx.y, d = threadIdx.x;
    const float* base = g_patches + (size_t)b * HWN * DD;
    float s = 0.f;
    for (int p = ch*128; p < ch*128 + 128; p++) s += base[(size_t)p * DD + d];
    g_partV[(b*8 + ch)*DD + d] = s;
}
__global__ void k_meant() {
    int ch = blockIdx.x, b = blockIdx.y, d = threadIdx.x;
    const float* base = g_tokens + (size_t)b * SS * DD;
    float s = 0.f;
    for (int p = ch*128; p < ch*128 + 128; p++) s += base[(size_t)p * DD + d];
    g_partT[(b*4 + ch)*DD + d] = s;
}

// ---------------- global adapters on pooled means ----------------
__global__ void k_gimg(const float* __restrict__ Wv, const float* __restrict__ bv) {
    __shared__ float sm[DD];
    int b = blockIdx.x, d = threadIdx.x;
    float s = 0.f;
#pragma unroll
    for (int ch = 0; ch < 8; ch++) s += g_partV[(b*8 + ch)*DD + d];
    sm[d] = s * (1.0f / (float)HWN);
    __syncthreads();
    float acc = bv[d];
    for (int c = 0; c < DD; c++) acc = fmaf(sm[c], Wv[(size_t)d * DD + c], acc);
    g_gimg[b*DD + d] = acc;
}
__global__ void k_gtxt(const float* __restrict__ Wt, const float* __restrict__ bt) {
    __shared__ float sm[DD];
    int b = blockIdx.x, d = threadIdx.x;
    float s = 0.f;
#pragma unroll
    for (int ch = 0; ch < 4; ch++) s += g_partT[(b*4 + ch)*DD + d];
    sm[d] = s * (1.0f / (float)SS);
    __syncthreads();
    float acc = bt[d];
    for (int c = 0; c < DD; c++) acc = fmaf(sm[c], Wt[(size_t)d * DD + c], acc);
    g_gtxt[b*DD + d] = acc;
}

// ---------------- global embedding norms ----------------
__global__ void k_gnorm() {
    int r = blockIdx.x, lane = threadIdx.x;
    const float* row = (r < 64) ? (g_gimg + (size_t)r * DD)
                                : (g_gtxt + (size_t)(r - 64) * DD);
    float s = 0.f;
#pragma unroll
    for (int q = 0; q < 8; q++) { float v = row[lane + q*32]; s += v*v; }
#pragma unroll
    for (int off = 16; off > 0; off >>= 1) s += __shfl_xor_sync(0xffffffffu, s, off);
    if (lane == 0) g_norms[r] = fmaxf(sqrtf(s), 1e-8f);
}

// ---------------- global sim matrix 64x64 ----------------
__global__ void k_gsim() {
    __shared__ float srow[DD];
    int i = blockIdx.x;
    int warp = threadIdx.x >> 5, lane = threadIdx.x & 31;
    for (int c = threadIdx.x; c < DD; c += 256) srow[c] = g_gimg[(size_t)i * DD + c];
    __syncthreads();
    float ni = g_norms[i];
    for (int j = warp; j < 64; j += 8) {
        const float* trow = g_gtxt + (size_t)j * DD;
        float s = 0.f;
#pragma unroll
        for (int q = 0; q < 8; q++) s += srow[lane + q*32] * trow[lane + q*32];
#pragma unroll
        for (int off = 16; off > 0; off >>= 1) s += __shfl_xor_sync(0xffffffffu, s, off);
        if (lane == 0)
            g_gsim[i*64 + j] = s / (ni * g_norms[64 + j]) * (1.0f / TAUV);
    }
}

// ---------------- global loss ----------------
__global__ void k_gloss() {
    __shared__ float sim[64][65];
    __shared__ float r1[64], r2[64];
    int t = threadIdx.x;  // 64 threads
    for (int idx = t; idx < 4096; idx += 64) sim[idx >> 6][idx & 63] = g_gsim[idx];
    __syncthreads();
    // row LSE
    float m = -1e30f;
    for (int j = 0; j < 64; j++) m = fmaxf(m, sim[t][j]);
    float s = 0.f;
    for (int j = 0; j < 64; j++) s += expf(sim[t][j] - m);
    r1[t] = m + logf(s) - sim[t][t];
    // col LSE
    m = -1e30f;
    for (int i = 0; i < 64; i++) m = fmaxf(m, sim[i][t]);
    s = 0.f;
    for (int i = 0; i < 64; i++) s += expf(sim[i][t] - m);
    r2[t] = m + logf(s) - sim[t][t];
    __syncthreads();
    if (t == 0) {
        float acc = 0.f;
        for (int r = 0; r < 64; r++) acc += r1[r] + r2[r];
        g_gloss = 0.5f * acc / 64.0f;
    }
}

// ---------------- fsim row / col LSE terms ----------------
__global__ void k_frow() {
    int warp = threadIdx.x >> 5, lane = threadIdx.x & 31;
    int r = blockIdx.x * 8 + warp;
    int b = r >> 9, i = r & (SS - 1);
    const float* row = g_fsim + ((size_t)b * SS + i) * SS;
    float v[16];
#pragma unroll
    for (int q = 0; q < 16; q++) v[q] = row[lane + q*32];
    float m = -1e30f;
#pragma unroll
    for (int q = 0; q < 16; q++) m = fmaxf(m, v[q]);
#pragma unroll
    for (int off = 16; off > 0; off >>= 1) m = fmaxf(m, __shfl_xor_sync(0xffffffffu, m, off));
    float s = 0.f;
#pragma unroll
    for (int q = 0; q < 16; q++) s += expf(v[q] - m);
#pragma unroll
    for (int off = 16; off > 0; off >>= 1) s += __shfl_xor_sync(0xffffffffu, s, off);
    if (lane == 0) g_rowterm[r] = m + logf(s) - row[i];
}

__global__ void k_fcol() {
    int b = blockIdx.y;
    int tx = threadIdx.x, ty = threadIdx.y;
    int j = blockIdx.x * 32 + tx;
    const float* Fb = g_fsim + (size_t)b * SS * SS;
    float m = -1e30f, s = 0.f;
    for (int i = ty; i < SS; i += 8) {
        float x = Fb[(size_t)i * SS + j];
        float nm = fmaxf(m, x);
        s = s * expf(m - nm) + expf(x - nm);
        m = nm;
    }
    __shared__ float sm[8][32], sv[8][32];
    sm[ty][tx] = m; sv[ty][tx] = s;
    __syncthreads();
    if (ty == 0) {
        float M = sm[0][tx], Sv = sv[0][tx];
#pragma unroll
        for (int q = 1; q < 8; q++) {
            float m2 = sm[q][tx], s2 = sv[q][tx];
            float nm = fmaxf(M, m2);
            Sv = Sv * expf(M - nm) + s2 * expf(m2 - nm);
            M = nm;
        }
        g_colterm[b*SS + j] = M + logf(Sv) - Fb[(size_t)j * SS + j];
    }
}

// ---------------- final scalar ----------------
__global__ void k_final(float* out) {
    __shared__ float red[256];
    int t = threadIdx.x;
    float s = 0.f;
    for (int idx = t; idx < BB*SS; idx += 256) s += g_rowterm[idx] + g_colterm[idx];
    red[t] = s;
    __syncthreads();
    for (int o = 128; o > 0; o >>= 1) {
        if (t < o) red[t] += red[t + o];
        __syncthreads();
    }
    if (t == 0) out[0] = g_gloss + 0.5f * red[0] / (float)(BB*SS);
}

// ---------------- launch ----------------
extern "C" void kernel_launch(void* const* d_in, const int* in_sizes, int n_in,
                              void* d_out, int out_size) {
    const float* img = (const float*)d_in[0];
    const float* txt = (const float*)d_in[1];
    const float* Wv  = (const float*)d_in[2];
    const float* bv  = (const float*)d_in[3];
    const float* Wt  = (const float*)d_in[4];
    const float* bt  = (const float*)d_in[5];
    float* out = (float*)d_out;

    k_patch_adapter<<<dim3(HWN/BM, DD/BN, BB), NTHR>>>(img, Wv, bv);
    k_tok_adapter  <<<dim3(SS/BM,  DD/BN, BB), NTHR>>>(txt, Wt, bt);

    // global path
    k_meanp<<<dim3(8, BB), 256>>>();
    k_gimg<<<BB, 256>>>(Wv, bv);
    k_meant<<<dim3(4, BB), 256>>>();
    k_gtxt<<<BB, 256>>>(Wt, bt);
    k_gnorm<<<128, 32>>>();
    k_gsim<<<64, 256>>>();
    k_gloss<<<1, 64>>>();

    // fine-grained path
    k_sim<<<dim3(HWN/BM, SS/BN, BB), NTHR>>>();
    k_colstats<<<dim3(SS/32, BB), dim3(32, 8)>>>();
    k_lgve<<<dim3(SS/BM, DD/BN, BB), NTHR>>>();
    k_l2norm<<<(BB*SS)/8, 256>>>(0);  // lgve -> lnv
    k_l2norm<<<(BB*SS)/8, 256>>>(1);  // tokens -> lnt
    k_fsim<<<dim3(SS/BM, SS/BN, BB), NTHR>>>();
    k_frow<<<(BB*SS)/8, 256>>>();
    k_fcol<<<dim3(SS/32, BB), dim3(32, 8)>>>();
    k_final<<<1, 256>>>(out);
}